// round 2
// baseline (speedup 1.0000x reference)
#include <cuda_runtime.h>
#include <math.h>

#define B 64
#define S 512
#define H 768
#define K 64

#define POOL_THREADS 384
#define POOL_SMEM (K * H * sizeof(float))   // 196608 bytes

// Scratch: pooled reps and hidden (post-tanh) per head.
__device__ float g_pooled[3 * B * H];
__device__ float g_h[3 * B * H];

// ---------------------------------------------------------------------------
// Kernel A: ragged self-attention pooling, smem-staged.
// grid (64, 3), block 384 (12 warps), dynamic smem 192KB (G tile).
// ---------------------------------------------------------------------------
__global__ void pool_kernel(const float* __restrict__ seq,
                            const int* __restrict__ idx0, const int* __restrict__ len0,
                            const int* __restrict__ idx1, const int* __restrict__ len1,
                            const int* __restrict__ idx2, const int* __restrict__ len2) {
    extern __shared__ float Gs[];            // [K][H]
    __shared__ float prob[K];
    __shared__ int   sidx[K];

    int b = blockIdx.x;
    int t = blockIdx.y;
    const int* idxp = (t == 0) ? idx0 : (t == 1) ? idx1 : idx2;
    const int* lenp = (t == 0) ? len0 : (t == 1) ? len1 : len2;
    int len = lenp[b];

    int tid  = threadIdx.x;
    int wid  = tid >> 5;
    int lane = tid & 31;

    if (tid < K) sidx[tid] = idxp[b * K + tid];
    __syncthreads();

    const float* seqb = seq + (size_t)b * S * H;

    // ---- Phase 0: gather G into smem (float4, high MLP) ----
    for (int j = wid; j < K; j += 12) {
        const float4* src = (const float4*)(seqb + (size_t)sidx[j] * H);
        float4* dst = (float4*)&Gs[j * H];
        #pragma unroll
        for (int i = 0; i < 6; i++) dst[lane + 32 * i] = src[lane + 32 * i];
    }
    __syncthreads();

    // ---- Phase 1: scores0[j] = dot(G0, Gj) from smem ----
    float g0r[24];
    #pragma unroll
    for (int i = 0; i < 24; i++) g0r[i] = Gs[lane + 32 * i];

    for (int j = wid; j < K; j += 12) {
        const float* gj = &Gs[j * H];
        float s = 0.f;
        #pragma unroll
        for (int i = 0; i < 24; i++) s += g0r[i] * gj[lane + 32 * i];
        #pragma unroll
        for (int o = 16; o; o >>= 1) s += __shfl_xor_sync(0xffffffffu, s, o);
        if (lane == 0) prob[j] = s;
    }
    __syncthreads();

    // ---- Phase 2: masked softmax over 64 (warp 0); zero-pad past len ----
    if (wid == 0) {
        float sa = (lane      < len) ? prob[lane]      : -1e30f;
        float sb = (lane + 32 < len) ? prob[lane + 32] : -1e30f;
        float m = fmaxf(sa, sb);
        #pragma unroll
        for (int o = 16; o; o >>= 1) m = fmaxf(m, __shfl_xor_sync(0xffffffffu, m, o));
        float ea = (lane      < len) ? expf(sa - m) : 0.f;
        float eb = (lane + 32 < len) ? expf(sb - m) : 0.f;
        float sum = ea + eb;
        #pragma unroll
        for (int o = 16; o; o >>= 1) sum += __shfl_xor_sync(0xffffffffu, sum, o);
        float inv = (sum > 0.f) ? (1.0f / sum) : 0.f;
        prob[lane]      = ea * inv;
        prob[lane + 32] = eb * inv;
    }
    __syncthreads();

    // ---- Phase 3: pooled[h] = sum_j prob[j] * G[j,h]; fixed 64-iter loop ----
    float ax = 0.f, ay = 0.f;
    #pragma unroll
    for (int j = 0; j < K; j++) {
        float a = prob[j];
        float2 g = *(const float2*)&Gs[j * H + 2 * tid];
        ax += a * g.x;
        ay += a * g.y;
    }
    if (len == 0) {   // fallback: seq[b, 0, :]
        ax = seqb[2 * tid];
        ay = seqb[2 * tid + 1];
    }
    *(float2*)&g_pooled[((size_t)t * B + b) * H + 2 * tid] = make_float2(ax, ay);
}

// ---------------------------------------------------------------------------
// Kernel B: h = tanh(P @ Wd^T + bd), tiled SGEMM.
// grid (12 rtiles of 64, 4 btiles of 16, 3 heads), block 128.
// Thread tile: rows {tx, tx+32} x 4 batches. Conflict-free LDS, FMA-bound.
// ---------------------------------------------------------------------------
__global__ void dense_kernel(const float* __restrict__ Wd0, const float* __restrict__ bd0,
                             const float* __restrict__ Wd1, const float* __restrict__ bd1,
                             const float* __restrict__ Wd2, const float* __restrict__ bd2) {
    int t = blockIdx.z;
    const float* Wd = (t == 0) ? Wd0 : (t == 1) ? Wd1 : Wd2;
    const float* bd = (t == 0) ? bd0 : (t == 1) ? bd1 : bd2;
    int r0 = blockIdx.x * 64;
    int b0 = blockIdx.y * 16;

    __shared__ float Ws[32][65];   // Ws[kk][r], padded: conflict-free
    __shared__ float Ps[16][32];   // Ps[bb][kk]

    int tid = threadIdx.x;
    int tx = tid & 31;    // rows tx, tx+32
    int ty = tid >> 5;    // batches ty*4 .. ty*4+3

    float acc0[4] = {0.f, 0.f, 0.f, 0.f};  // row tx
    float acc1[4] = {0.f, 0.f, 0.f, 0.f};  // row tx+32

    const float* P = g_pooled + (size_t)t * B * H;

    for (int k0 = 0; k0 < H; k0 += 32) {
        // stage Wd[r0+r][k0+kk] -> Ws[kk][r]  (2048 elems, 16/thread)
        #pragma unroll
        for (int i = 0; i < 16; i++) {
            int id = tid + 128 * i;
            int r  = id >> 5;
            int kk = id & 31;
            Ws[kk][r] = Wd[(size_t)(r0 + r) * H + (k0 + kk)];
        }
        // stage P[b0+bb][k0+kk] -> Ps[bb][kk]  (512 elems, 4/thread)
        #pragma unroll
        for (int i = 0; i < 4; i++) {
            int id = tid + 128 * i;
            int bb = id >> 5;
            int kk = id & 31;
            Ps[bb][kk] = P[(size_t)(b0 + bb) * H + (k0 + kk)];
        }
        __syncthreads();

        #pragma unroll
        for (int kk4 = 0; kk4 < 32; kk4 += 4) {
            float4 p0 = *(const float4*)&Ps[ty * 4 + 0][kk4];
            float4 p1 = *(const float4*)&Ps[ty * 4 + 1][kk4];
            float4 p2 = *(const float4*)&Ps[ty * 4 + 2][kk4];
            float4 p3 = *(const float4*)&Ps[ty * 4 + 3][kk4];
            #pragma unroll
            for (int u = 0; u < 4; u++) {
                float w0 = Ws[kk4 + u][tx];
                float w1 = Ws[kk4 + u][tx + 32];
                float pu0 = (&p0.x)[u], pu1 = (&p1.x)[u];
                float pu2 = (&p2.x)[u], pu3 = (&p3.x)[u];
                acc0[0] += pu0 * w0;  acc1[0] += pu0 * w1;
                acc0[1] += pu1 * w0;  acc1[1] += pu1 * w1;
                acc0[2] += pu2 * w0;  acc1[2] += pu2 * w1;
                acc0[3] += pu3 * w0;  acc1[3] += pu3 * w1;
            }
        }
        __syncthreads();
    }

    int ra = r0 + tx;
    int rb = r0 + tx + 32;
    float bda = bd[ra];
    float bdb = bd[rb];
    #pragma unroll
    for (int bb = 0; bb < 4; bb++) {
        int bidx = b0 + ty * 4 + bb;
        float* hrow = &g_h[((size_t)t * B + bidx) * H];
        hrow[ra] = tanhf(acc0[bb] + bda);
        hrow[rb] = tanhf(acc1[bb] + bdb);
    }
}

// ---------------------------------------------------------------------------
// Kernel C: logits = h @ Wc^T + bc. grid (64, 3), block 288 (9 warps).
// Output layout: [rel 64x9 | nov 64x3 | dir 64x3]
// ---------------------------------------------------------------------------
__global__ void cls_kernel(const float* __restrict__ Wc0, const float* __restrict__ bc0,
                           const float* __restrict__ Wc1, const float* __restrict__ bc1,
                           const float* __restrict__ Wc2, const float* __restrict__ bc2,
                           float* __restrict__ out) {
    int b = blockIdx.x;
    int t = blockIdx.y;
    const float* Wc = (t == 0) ? Wc0 : (t == 1) ? Wc1 : Wc2;
    const float* bc = (t == 0) ? bc0 : (t == 1) ? bc1 : bc2;
    int nlab   = (t == 0) ? 9 : 3;
    int outoff = (t == 0) ? 0 : (t == 1) ? B * 9 : B * 9 + B * 3;

    int w = threadIdx.x >> 5;
    int lane = threadIdx.x & 31;
    if (w >= nlab) return;

    const float* h = g_h + ((size_t)t * B + b) * H;
    const float* wrow = Wc + (size_t)w * H;
    float s = 0.f;
    #pragma unroll
    for (int k = lane; k < H; k += 32) s += h[k] * wrow[k];
    #pragma unroll
    for (int o = 16; o; o >>= 1) s += __shfl_xor_sync(0xffffffffu, s, o);
    if (lane == 0) out[outoff + b * nlab + w] = s + bc[w];
}

// ---------------------------------------------------------------------------
extern "C" void kernel_launch(void* const* d_in, const int* in_sizes, int n_in,
                              void* d_out, int out_size) {
    const float* seq      = (const float*)d_in[0];
    const int*   rel_idx  = (const int*)d_in[1];
    const int*   rel_len  = (const int*)d_in[2];
    const int*   nov_idx  = (const int*)d_in[3];
    const int*   nov_len  = (const int*)d_in[4];
    const int*   dir_idx  = (const int*)d_in[5];
    const int*   dir_len  = (const int*)d_in[6];
    const float* rel_dW   = (const float*)d_in[7];
    const float* rel_db   = (const float*)d_in[8];
    const float* rel_cW   = (const float*)d_in[9];
    const float* rel_cb   = (const float*)d_in[10];
    const float* nov_dW   = (const float*)d_in[11];
    const float* nov_db   = (const float*)d_in[12];
    const float* nov_cW   = (const float*)d_in[13];
    const float* nov_cb   = (const float*)d_in[14];
    const float* dir_dW   = (const float*)d_in[15];
    const float* dir_db   = (const float*)d_in[16];
    const float* dir_cW   = (const float*)d_in[17];
    const float* dir_cb   = (const float*)d_in[18];
    float* out = (float*)d_out;

    static int smem_set = 0;
    if (!smem_set) {
        cudaFuncSetAttribute(pool_kernel,
                             cudaFuncAttributeMaxDynamicSharedMemorySize,
                             POOL_SMEM);
        smem_set = 1;
    }

    pool_kernel<<<dim3(B, 3), POOL_THREADS, POOL_SMEM>>>(
        seq, rel_idx, rel_len, nov_idx, nov_len, dir_idx, dir_len);
    dense_kernel<<<dim3(12, 4, 3), 128>>>(rel_dW, rel_db, nov_dW, nov_db,
                                          dir_dW, dir_db);
    cls_kernel<<<dim3(B, 3), 288>>>(rel_cW, rel_cb, nov_cW, nov_cb,
                                    dir_cW, dir_cb, out);
}

// round 3
// speedup vs baseline: 1.1900x; 1.1900x over previous
#include <cuda_runtime.h>
#include <math.h>

#define B 64
#define S 512
#define H 768
#define K 64

// Scratch
__device__ float g_scores[3 * B * K];
__device__ float g_pooled[3 * B * H];
__device__ float g_h[3 * B * H];

// ---------------------------------------------------------------------------
// K1: raw scores[j] = dot(G0, Gj). grid (B, 3, 4), block 256 (8 warps).
// Each block handles 16 j's; each warp 2 j's. Pure streaming gather.
// ---------------------------------------------------------------------------
__global__ void score_kernel(const float* __restrict__ seq,
                             const int* __restrict__ idx0,
                             const int* __restrict__ idx1,
                             const int* __restrict__ idx2) {
    int b  = blockIdx.x;
    int t  = blockIdx.y;
    int jt = blockIdx.z;           // 16 j's per block
    const int* idxp = (t == 0) ? idx0 : (t == 1) ? idx1 : idx2;

    __shared__ int sidx[16];
    __shared__ int si0;

    int tid  = threadIdx.x;
    int wid  = tid >> 5;
    int lane = tid & 31;

    if (tid < 16) sidx[tid] = idxp[b * K + jt * 16 + tid];
    if (tid == 16) si0 = idxp[b * K];
    __syncthreads();

    const float* seqb = seq + (size_t)b * S * H;

    // row 0 into registers (float4 x6 per lane)
    float4 g0v[6];
    const float4* r0 = (const float4*)(seqb + (size_t)si0 * H);
    #pragma unroll
    for (int i = 0; i < 6; i++) g0v[i] = r0[lane + 32 * i];

    #pragma unroll
    for (int jj = wid; jj < 16; jj += 8) {
        const float4* gj = (const float4*)(seqb + (size_t)sidx[jj] * H);
        float s = 0.f;
        #pragma unroll
        for (int i = 0; i < 6; i++) {
            float4 gv = gj[lane + 32 * i];
            s += g0v[i].x * gv.x + g0v[i].y * gv.y
               + g0v[i].z * gv.z + g0v[i].w * gv.w;
        }
        #pragma unroll
        for (int o = 16; o; o >>= 1) s += __shfl_xor_sync(0xffffffffu, s, o);
        if (lane == 0) g_scores[((size_t)t * B + b) * K + jt * 16 + jj] = s;
    }
}

// ---------------------------------------------------------------------------
// K2: softmax + weighted sum. grid (B, 3, 4 htiles of 192), block 192.
// Re-reads gathered rows from L2 (hot from K1).
// ---------------------------------------------------------------------------
__global__ void pool_kernel(const float* __restrict__ seq,
                            const int* __restrict__ idx0, const int* __restrict__ len0,
                            const int* __restrict__ idx1, const int* __restrict__ len1,
                            const int* __restrict__ idx2, const int* __restrict__ len2) {
    int b  = blockIdx.x;
    int t  = blockIdx.y;
    int h0 = blockIdx.z * 192;
    const int* idxp = (t == 0) ? idx0 : (t == 1) ? idx1 : idx2;
    const int* lenp = (t == 0) ? len0 : (t == 1) ? len1 : len2;

    __shared__ float prob[K];
    __shared__ int   sidx[K];

    int tid  = threadIdx.x;
    int lane = tid & 31;
    int len  = lenp[b];

    if (tid < K) sidx[tid] = idxp[b * K + tid];

    if (tid < 32) {  // warp 0: masked softmax over 64 scores
        const float* sc = &g_scores[((size_t)t * B + b) * K];
        float sa = (lane      < len) ? sc[lane]      : -1e30f;
        float sb = (lane + 32 < len) ? sc[lane + 32] : -1e30f;
        float m = fmaxf(sa, sb);
        #pragma unroll
        for (int o = 16; o; o >>= 1) m = fmaxf(m, __shfl_xor_sync(0xffffffffu, m, o));
        float ea = (lane      < len) ? expf(sa - m) : 0.f;
        float eb = (lane + 32 < len) ? expf(sb - m) : 0.f;
        float sum = ea + eb;
        #pragma unroll
        for (int o = 16; o; o >>= 1) sum += __shfl_xor_sync(0xffffffffu, sum, o);
        float inv = (sum > 0.f) ? (1.0f / sum) : 0.f;
        prob[lane]      = ea * inv;
        prob[lane + 32] = eb * inv;
    }
    __syncthreads();

    const float* base = seq + (size_t)b * S * H + h0 + tid;
    float acc = 0.f;
    #pragma unroll 8
    for (int j = 0; j < K; j++) {
        acc += prob[j] * base[(size_t)sidx[j] * H];
    }
    if (len == 0) acc = base[0];   // fallback: seq[b, 0, :]
    g_pooled[((size_t)t * B + b) * H + h0 + tid] = acc;
}

// ---------------------------------------------------------------------------
// Kernel B: h = tanh(P @ Wd^T + bd), tiled SGEMM (R1 version, proven).
// grid (12 rtiles of 64, 4 btiles of 16, 3 heads), block 128.
// ---------------------------------------------------------------------------
__global__ void dense_kernel(const float* __restrict__ Wd0, const float* __restrict__ bd0,
                             const float* __restrict__ Wd1, const float* __restrict__ bd1,
                             const float* __restrict__ Wd2, const float* __restrict__ bd2) {
    int t = blockIdx.z;
    const float* Wd = (t == 0) ? Wd0 : (t == 1) ? Wd1 : Wd2;
    const float* bd = (t == 0) ? bd0 : (t == 1) ? bd1 : bd2;
    int r0 = blockIdx.x * 64;
    int b0 = blockIdx.y * 16;

    __shared__ float Ws[32][66];   // transposed Wd tile: Ws[kk][r], padded
    __shared__ float Ps[16][32];   // pooled tile: Ps[bb][kk]

    int tid = threadIdx.x;
    int tx = tid & 31;    // -> rows 2*tx, 2*tx+1
    int ty = tid >> 5;    // -> batches ty*4 .. ty*4+3

    float acc[4][2];
    #pragma unroll
    for (int i = 0; i < 4; i++) { acc[i][0] = 0.f; acc[i][1] = 0.f; }

    const float* P = g_pooled + (size_t)t * B * H;

    for (int k0 = 0; k0 < H; k0 += 32) {
        #pragma unroll
        for (int i = 0; i < 16; i++) {
            int id = tid + 128 * i;
            int r  = id >> 5;
            int kk = id & 31;
            Ws[kk][r] = Wd[(size_t)(r0 + r) * H + (k0 + kk)];
        }
        #pragma unroll
        for (int i = 0; i < 4; i++) {
            int id = tid + 128 * i;
            int bb = id >> 5;
            int kk = id & 31;
            Ps[bb][kk] = P[(size_t)(b0 + bb) * H + (k0 + kk)];
        }
        __syncthreads();

        #pragma unroll
        for (int kk = 0; kk < 32; kk++) {
            float w0 = Ws[kk][2 * tx];
            float w1 = Ws[kk][2 * tx + 1];
            #pragma unroll
            for (int bb = 0; bb < 4; bb++) {
                float p = Ps[ty * 4 + bb][kk];
                acc[bb][0] += p * w0;
                acc[bb][1] += p * w1;
            }
        }
        __syncthreads();
    }

    int r = r0 + 2 * tx;
    float bdr0 = bd[r];
    float bdr1 = bd[r + 1];
    #pragma unroll
    for (int bb = 0; bb < 4; bb++) {
        int bidx = b0 + ty * 4 + bb;
        float2 hv;
        hv.x = tanhf(acc[bb][0] + bdr0);
        hv.y = tanhf(acc[bb][1] + bdr1);
        *reinterpret_cast<float2*>(&g_h[((size_t)t * B + bidx) * H + r]) = hv;
    }
}

// ---------------------------------------------------------------------------
// Kernel C: logits = h @ Wc^T + bc. grid (64, 3), block 288 (9 warps).
// Output layout: [rel 64x9 | nov 64x3 | dir 64x3]
// ---------------------------------------------------------------------------
__global__ void cls_kernel(const float* __restrict__ Wc0, const float* __restrict__ bc0,
                           const float* __restrict__ Wc1, const float* __restrict__ bc1,
                           const float* __restrict__ Wc2, const float* __restrict__ bc2,
                           float* __restrict__ out) {
    int b = blockIdx.x;
    int t = blockIdx.y;
    const float* Wc = (t == 0) ? Wc0 : (t == 1) ? Wc1 : Wc2;
    const float* bc = (t == 0) ? bc0 : (t == 1) ? bc1 : bc2;
    int nlab   = (t == 0) ? 9 : 3;
    int outoff = (t == 0) ? 0 : (t == 1) ? B * 9 : B * 9 + B * 3;

    int w = threadIdx.x >> 5;
    int lane = threadIdx.x & 31;
    if (w >= nlab) return;

    const float* h = g_h + ((size_t)t * B + b) * H;
    const float* wrow = Wc + (size_t)w * H;
    float s = 0.f;
    #pragma unroll
    for (int k = lane; k < H; k += 32) s += h[k] * wrow[k];
    #pragma unroll
    for (int o = 16; o; o >>= 1) s += __shfl_xor_sync(0xffffffffu, s, o);
    if (lane == 0) out[outoff + b * nlab + w] = s + bc[w];
}

// ---------------------------------------------------------------------------
extern "C" void kernel_launch(void* const* d_in, const int* in_sizes, int n_in,
                              void* d_out, int out_size) {
    const float* seq      = (const float*)d_in[0];
    const int*   rel_idx  = (const int*)d_in[1];
    const int*   rel_len  = (const int*)d_in[2];
    const int*   nov_idx  = (const int*)d_in[3];
    const int*   nov_len  = (const int*)d_in[4];
    const int*   dir_idx  = (const int*)d_in[5];
    const int*   dir_len  = (const int*)d_in[6];
    const float* rel_dW   = (const float*)d_in[7];
    const float* rel_db   = (const float*)d_in[8];
    const float* rel_cW   = (const float*)d_in[9];
    const float* rel_cb   = (const float*)d_in[10];
    const float* nov_dW   = (const float*)d_in[11];
    const float* nov_db   = (const float*)d_in[12];
    const float* nov_cW   = (const float*)d_in[13];
    const float* nov_cb   = (const float*)d_in[14];
    const float* dir_dW   = (const float*)d_in[15];
    const float* dir_db   = (const float*)d_in[16];
    const float* dir_cW   = (const float*)d_in[17];
    const float* dir_cb   = (const float*)d_in[18];
    float* out = (float*)d_out;

    score_kernel<<<dim3(B, 3, 4), 256>>>(seq, rel_idx, nov_idx, dir_idx);
    pool_kernel<<<dim3(B, 3, 4), 192>>>(seq, rel_idx, rel_len, nov_idx, nov_len,
                                        dir_idx, dir_len);
    dense_kernel<<<dim3(12, 4, 3), 128>>>(rel_dW, rel_db, nov_dW, nov_db,
                                          dir_dW, dir_db);
    cls_kernel<<<dim3(B, 3), 288>>>(rel_cW, rel_cb, nov_cW, nov_cb,
                                    dir_cW, dir_cb, out);
}

// round 4
// speedup vs baseline: 1.3847x; 1.1637x over previous
#include <cuda_runtime.h>
#include <math.h>

#define B 64
#define S 512
#define H 768
#define K 64

// Scratch
__device__ float g_scores[3 * B * K];
__device__ float g_pooled[3 * B * H];

// ---------------------------------------------------------------------------
// K1: raw scores[j] = dot(G0, Gj). grid (B, 3, 4), block 256 (8 warps).
// Block (0,0,0) additionally initializes out[] with classifier biases.
// ---------------------------------------------------------------------------
__global__ void score_kernel(const float* __restrict__ seq,
                             const int* __restrict__ idx0,
                             const int* __restrict__ idx1,
                             const int* __restrict__ idx2,
                             const float* __restrict__ bc0,
                             const float* __restrict__ bc1,
                             const float* __restrict__ bc2,
                             float* __restrict__ out) {
    int b  = blockIdx.x;
    int t  = blockIdx.y;
    int jt = blockIdx.z;           // 16 j's per block
    const int* idxp = (t == 0) ? idx0 : (t == 1) ? idx1 : idx2;

    __shared__ int sidx[16];
    __shared__ int si0;

    int tid  = threadIdx.x;
    int wid  = tid >> 5;
    int lane = tid & 31;

    // bias init of the output buffer (layout: rel 64x9 | nov 64x3 | dir 64x3)
    if (b == 0 && t == 0 && jt == 0) {
        for (int i = tid; i < 960; i += 256) {
            float v;
            if (i < 576)      v = bc0[i % 9];
            else if (i < 768) v = bc1[(i - 576) % 3];
            else              v = bc2[(i - 768) % 3];
            out[i] = v;
        }
    }

    if (tid < 16) sidx[tid] = idxp[b * K + jt * 16 + tid];
    if (tid == 16) si0 = idxp[b * K];
    __syncthreads();

    const float* seqb = seq + (size_t)b * S * H;

    float4 g0v[6];
    const float4* r0 = (const float4*)(seqb + (size_t)si0 * H);
    #pragma unroll
    for (int i = 0; i < 6; i++) g0v[i] = r0[lane + 32 * i];

    #pragma unroll
    for (int jj = wid; jj < 16; jj += 8) {
        const float4* gj = (const float4*)(seqb + (size_t)sidx[jj] * H);
        float s = 0.f;
        #pragma unroll
        for (int i = 0; i < 6; i++) {
            float4 gv = gj[lane + 32 * i];
            s += g0v[i].x * gv.x + g0v[i].y * gv.y
               + g0v[i].z * gv.z + g0v[i].w * gv.w;
        }
        #pragma unroll
        for (int o = 16; o; o >>= 1) s += __shfl_xor_sync(0xffffffffu, s, o);
        if (lane == 0) g_scores[((size_t)t * B + b) * K + jt * 16 + jj] = s;
    }
}

// ---------------------------------------------------------------------------
// K2: softmax + weighted sum. grid (B, 3, 4 htiles of 192), block 192.
// ---------------------------------------------------------------------------
__global__ void pool_kernel(const float* __restrict__ seq,
                            const int* __restrict__ idx0, const int* __restrict__ len0,
                            const int* __restrict__ idx1, const int* __restrict__ len1,
                            const int* __restrict__ idx2, const int* __restrict__ len2) {
    int b  = blockIdx.x;
    int t  = blockIdx.y;
    int h0 = blockIdx.z * 192;
    const int* idxp = (t == 0) ? idx0 : (t == 1) ? idx1 : idx2;
    const int* lenp = (t == 0) ? len0 : (t == 1) ? len1 : len2;

    __shared__ float prob[K];
    __shared__ int   sidx[K];

    int tid  = threadIdx.x;
    int lane = tid & 31;
    int len  = lenp[b];

    if (tid < K) sidx[tid] = idxp[b * K + tid];

    if (tid < 32) {  // warp 0: masked softmax over 64 scores
        const float* sc = &g_scores[((size_t)t * B + b) * K];
        float sa = (lane      < len) ? sc[lane]      : -1e30f;
        float sb = (lane + 32 < len) ? sc[lane + 32] : -1e30f;
        float m = fmaxf(sa, sb);
        #pragma unroll
        for (int o = 16; o; o >>= 1) m = fmaxf(m, __shfl_xor_sync(0xffffffffu, m, o));
        float ea = (lane      < len) ? expf(sa - m) : 0.f;
        float eb = (lane + 32 < len) ? expf(sb - m) : 0.f;
        float sum = ea + eb;
        #pragma unroll
        for (int o = 16; o; o >>= 1) sum += __shfl_xor_sync(0xffffffffu, sum, o);
        float inv = (sum > 0.f) ? (1.0f / sum) : 0.f;
        prob[lane]      = ea * inv;
        prob[lane + 32] = eb * inv;
    }
    __syncthreads();

    const float* base = seq + (size_t)b * S * H + h0 + tid;
    float acc = 0.f;
    #pragma unroll 16
    for (int j = 0; j < K; j++) {
        acc += prob[j] * base[(size_t)sidx[j] * H];
    }
    if (len == 0) acc = base[0];   // fallback: seq[b, 0, :]
    g_pooled[((size_t)t * B + b) * H + h0 + tid] = acc;
}

// ---------------------------------------------------------------------------
// K3: h = tanh(P @ Wd^T + bd) tile, then fused classifier partials via atomics.
// grid (12 rtiles of 64, 4 btiles of 16, 3 heads), block 256.
// Thread GEMM tile: rows {2tx, 2tx+1} x batches {2ty, 2ty+1}.
// ---------------------------------------------------------------------------
__global__ void dense_kernel(const float* __restrict__ Wd0, const float* __restrict__ bd0,
                             const float* __restrict__ Wd1, const float* __restrict__ bd1,
                             const float* __restrict__ Wd2, const float* __restrict__ bd2,
                             const float* __restrict__ Wc0,
                             const float* __restrict__ Wc1,
                             const float* __restrict__ Wc2,
                             float* __restrict__ out) {
    int t = blockIdx.z;
    const float* Wd = (t == 0) ? Wd0 : (t == 1) ? Wd1 : Wd2;
    const float* bd = (t == 0) ? bd0 : (t == 1) ? bd1 : bd2;
    const float* Wc = (t == 0) ? Wc0 : (t == 1) ? Wc1 : Wc2;
    int nlab   = (t == 0) ? 9 : 3;
    int outoff = (t == 0) ? 0 : (t == 1) ? B * 9 : B * 9 + B * 3;

    int r0 = blockIdx.x * 64;
    int b0 = blockIdx.y * 16;

    __shared__ float Ws[32][66];   // Ws[kk][r]
    __shared__ float Ps[16][32];   // Ps[bb][kk]
    __shared__ float Hs[16][66];   // h tile, batch-major

    int tid = threadIdx.x;
    int tx = tid & 31;    // rows 2tx, 2tx+1
    int ty = tid >> 5;    // batches 2ty, 2ty+1

    float acc[2][2] = {{0.f, 0.f}, {0.f, 0.f}};   // [batch][row]

    const float* P = g_pooled + (size_t)t * B * H;

    for (int k0 = 0; k0 < H; k0 += 32) {
        #pragma unroll
        for (int i = 0; i < 8; i++) {
            int id = tid + 256 * i;
            int r  = id >> 5;
            int kk = id & 31;
            Ws[kk][r] = Wd[(size_t)(r0 + r) * H + (k0 + kk)];
        }
        #pragma unroll
        for (int i = 0; i < 2; i++) {
            int id = tid + 256 * i;
            int bb = id >> 5;
            int kk = id & 31;
            Ps[bb][kk] = P[(size_t)(b0 + bb) * H + (k0 + kk)];
        }
        __syncthreads();

        #pragma unroll
        for (int kk = 0; kk < 32; kk++) {
            float w0 = Ws[kk][2 * tx];
            float w1 = Ws[kk][2 * tx + 1];
            float p0 = Ps[2 * ty][kk];
            float p1 = Ps[2 * ty + 1][kk];
            acc[0][0] += p0 * w0;  acc[0][1] += p0 * w1;
            acc[1][0] += p1 * w0;  acc[1][1] += p1 * w1;
        }
        __syncthreads();
    }

    int r = 2 * tx;
    float bdr0 = bd[r0 + r];
    float bdr1 = bd[r0 + r + 1];
    #pragma unroll
    for (int bb = 0; bb < 2; bb++) {
        Hs[2 * ty + bb][r]     = tanhf(acc[bb][0] + bdr0);
        Hs[2 * ty + bb][r + 1] = tanhf(acc[bb][1] + bdr1);
    }
    __syncthreads();

    // Fused classifier: warp ty handles batches 2ty, 2ty+1.
    int lane = tx;
    #pragma unroll
    for (int bb = 0; bb < 2; bb++) {
        int bl = 2 * ty + bb;
        float h0v = Hs[bl][lane];
        float h1v = Hs[bl][lane + 32];
        for (int l = 0; l < nlab; l++) {
            const float* wr = Wc + (size_t)l * H + r0;
            float s = h0v * __ldg(wr + lane) + h1v * __ldg(wr + lane + 32);
            #pragma unroll
            for (int o = 16; o; o >>= 1) s += __shfl_xor_sync(0xffffffffu, s, o);
            if (lane == 0)
                atomicAdd(&out[outoff + (b0 + bl) * nlab + l], s);
        }
    }
}

// ---------------------------------------------------------------------------
extern "C" void kernel_launch(void* const* d_in, const int* in_sizes, int n_in,
                              void* d_out, int out_size) {
    const float* seq      = (const float*)d_in[0];
    const int*   rel_idx  = (const int*)d_in[1];
    const int*   rel_len  = (const int*)d_in[2];
    const int*   nov_idx  = (const int*)d_in[3];
    const int*   nov_len  = (const int*)d_in[4];
    const int*   dir_idx  = (const int*)d_in[5];
    const int*   dir_len  = (const int*)d_in[6];
    const float* rel_dW   = (const float*)d_in[7];
    const float* rel_db   = (const float*)d_in[8];
    const float* rel_cW   = (const float*)d_in[9];
    const float* rel_cb   = (const float*)d_in[10];
    const float* nov_dW   = (const float*)d_in[11];
    const float* nov_db   = (const float*)d_in[12];
    const float* nov_cW   = (const float*)d_in[13];
    const float* nov_cb   = (const float*)d_in[14];
    const float* dir_dW   = (const float*)d_in[15];
    const float* dir_db   = (const float*)d_in[16];
    const float* dir_cW   = (const float*)d_in[17];
    const float* dir_cb   = (const float*)d_in[18];
    float* out = (float*)d_out;

    score_kernel<<<dim3(B, 3, 4), 256>>>(seq, rel_idx, nov_idx, dir_idx,
                                         rel_cb, nov_cb, dir_cb, out);
    pool_kernel<<<dim3(B, 3, 4), 192>>>(seq, rel_idx, rel_len, nov_idx, nov_len,
                                        dir_idx, dir_len);
    dense_kernel<<<dim3(12, 4, 3), 256>>>(rel_dW, rel_db, nov_dW, nov_db,
                                          dir_dW, dir_db,
                                          rel_cW, nov_cW, dir_cW, out);
}